// round 1
// baseline (speedup 1.0000x reference)
#include <cuda_runtime.h>
#include <math.h>
#include <float.h>

// Problem constants
#define Bc 2
#define Lc 1024
#define Dc 1024
#define Hc 16
#define NLAYER 8
#define Vc 32000
#define Fc 4096
#define DHc 64

// ---------------------------------------------------------------------------
// Device-global scratch (no runtime allocation allowed)
// ---------------------------------------------------------------------------
__device__ float g_y[Bc * Lc * Dc];      // residual stream
__device__ float g_x[Bc * Lc * Dc];      // rmsnorm output
__device__ float g_q[Bc * Lc * Dc];
__device__ float g_k[Bc * Lc * Dc];
__device__ float g_v[Bc * Lc * Dc];
__device__ float g_t[Bc * Lc * Dc];      // attention output (pre-Wo)
__device__ float g_att[Bc * Hc * Lc * Lc];  // attention scores/probs (128 MB)
__device__ float g_g[Bc * Lc * Fc];      // FFN gate / fused hidden
__device__ float g_p[Bc * Lc * Fc];      // FFN proj

// ---------------------------------------------------------------------------
// Block reductions
// ---------------------------------------------------------------------------
__device__ __forceinline__ float blockReduceSum(float v) {
    __shared__ float sh[33];
    int lane = threadIdx.x & 31, wid = threadIdx.x >> 5;
    #pragma unroll
    for (int o = 16; o > 0; o >>= 1) v += __shfl_down_sync(0xffffffffu, v, o);
    if (lane == 0) sh[wid] = v;
    __syncthreads();
    v = (threadIdx.x < (blockDim.x >> 5)) ? sh[lane] : 0.0f;
    if (wid == 0) {
        #pragma unroll
        for (int o = 16; o > 0; o >>= 1) v += __shfl_down_sync(0xffffffffu, v, o);
        if (lane == 0) sh[32] = v;
    }
    __syncthreads();
    return sh[32];
}

__device__ __forceinline__ float blockReduceMax(float v) {
    __shared__ float sh[33];
    int lane = threadIdx.x & 31, wid = threadIdx.x >> 5;
    #pragma unroll
    for (int o = 16; o > 0; o >>= 1) v = fmaxf(v, __shfl_down_sync(0xffffffffu, v, o));
    if (lane == 0) sh[wid] = v;
    __syncthreads();
    v = (threadIdx.x < (blockDim.x >> 5)) ? sh[lane] : -FLT_MAX;
    if (wid == 0) {
        #pragma unroll
        for (int o = 16; o > 0; o >>= 1) v = fmaxf(v, __shfl_down_sync(0xffffffffu, v, o));
        if (lane == 0) sh[32] = v;
    }
    __syncthreads();
    return sh[32];
}

// ---------------------------------------------------------------------------
// Tiled SGEMM: C[M,N] = A[M,K] @ B[K,N]  (+ optional residual R, same layout as C)
// BM=128, BN=64, BK=8, 256 threads, 8x4 per thread.
// Batched via blockIdx.z decomposed as (zb, zh) with zh = z % bH.
// ---------------------------------------------------------------------------
#define GBM 128
#define GBN 64
#define GBK 8

__global__ __launch_bounds__(256) void sgemm_nn(
    const float* __restrict__ A, const float* __restrict__ B,
    float* __restrict__ C, const float* __restrict__ R,
    int K, int lda, int ldb, int ldc,
    int bH, long sAb, long sAh, long sBb, long sBh, long sCb, long sCh)
{
    int z = blockIdx.z;
    int zb = z / bH, zh = z - zb * bH;
    A += (long)zb * sAb + (long)zh * sAh;
    B += (long)zb * sBb + (long)zh * sBh;
    long coff = (long)zb * sCb + (long)zh * sCh;
    C += coff;
    if (R) R += coff;

    __shared__ float As[GBK][GBM];
    __shared__ float Bs[GBK][GBN];

    int tid = threadIdx.x;
    int row0 = blockIdx.y * GBM, col0 = blockIdx.x * GBN;

    int ar = tid >> 1;              // 0..127
    int ak = (tid & 1) << 2;        // 0 or 4
    int bk = tid >> 4;              // valid when tid<128: 0..7
    int bn = (tid & 15) << 2;       // 0..60
    int tr = tid >> 4, tc = tid & 15;

    float acc[8][4];
    #pragma unroll
    for (int i = 0; i < 8; i++)
        #pragma unroll
        for (int j = 0; j < 4; j++) acc[i][j] = 0.0f;

    const float* Aptr = A + (long)(row0 + ar) * lda + ak;
    const float* Bptr = B + (long)bk * ldb + col0 + bn;

    for (int k0 = 0; k0 < K; k0 += GBK) {
        float4 av = *(const float4*)(Aptr + k0);
        As[ak + 0][ar] = av.x; As[ak + 1][ar] = av.y;
        As[ak + 2][ar] = av.z; As[ak + 3][ar] = av.w;
        if (tid < 128) {
            float4 bv = *(const float4*)(Bptr + (long)k0 * ldb);
            *(float4*)&Bs[bk][bn] = bv;
        }
        __syncthreads();
        #pragma unroll
        for (int kk = 0; kk < GBK; kk++) {
            float4 a0 = *(const float4*)&As[kk][tr * 8];
            float4 a1 = *(const float4*)&As[kk][tr * 8 + 4];
            float4 b0 = *(const float4*)&Bs[kk][tc * 4];
            float a[8] = {a0.x, a0.y, a0.z, a0.w, a1.x, a1.y, a1.z, a1.w};
            float b[4] = {b0.x, b0.y, b0.z, b0.w};
            #pragma unroll
            for (int i = 0; i < 8; i++)
                #pragma unroll
                for (int j = 0; j < 4; j++) acc[i][j] = fmaf(a[i], b[j], acc[i][j]);
        }
        __syncthreads();
    }

    #pragma unroll
    for (int i = 0; i < 8; i++) {
        long off = (long)(row0 + tr * 8 + i) * ldc + col0 + tc * 4;
        float4 res = make_float4(acc[i][0], acc[i][1], acc[i][2], acc[i][3]);
        if (R) {
            float4 rv = *(const float4*)(R + off);
            res.x += rv.x; res.y += rv.y; res.z += rv.z; res.w += rv.w;
        }
        *(float4*)(C + off) = res;
    }
}

// NT variant: C[M,N] = A[M,K] @ B[N,K]^T  (B row-major N x K)
__global__ __launch_bounds__(256) void sgemm_nt(
    const float* __restrict__ A, const float* __restrict__ B,
    float* __restrict__ C,
    int K, int lda, int ldb, int ldc,
    int bH, long sAb, long sAh, long sBb, long sBh, long sCb, long sCh)
{
    int z = blockIdx.z;
    int zb = z / bH, zh = z - zb * bH;
    A += (long)zb * sAb + (long)zh * sAh;
    B += (long)zb * sBb + (long)zh * sBh;
    C += (long)zb * sCb + (long)zh * sCh;

    __shared__ float As[GBK][GBM];
    __shared__ float Bs[GBK][GBN];

    int tid = threadIdx.x;
    int row0 = blockIdx.y * GBM, col0 = blockIdx.x * GBN;

    int ar = tid >> 1;
    int ak = (tid & 1) << 2;
    int bnr = tid >> 1;             // valid when tid<128: 0..63
    int bks = (tid & 1) << 2;
    int tr = tid >> 4, tc = tid & 15;

    float acc[8][4];
    #pragma unroll
    for (int i = 0; i < 8; i++)
        #pragma unroll
        for (int j = 0; j < 4; j++) acc[i][j] = 0.0f;

    const float* Aptr = A + (long)(row0 + ar) * lda + ak;
    const float* Bptr = B + (long)(col0 + (bnr & 63)) * ldb + bks;

    for (int k0 = 0; k0 < K; k0 += GBK) {
        float4 av = *(const float4*)(Aptr + k0);
        As[ak + 0][ar] = av.x; As[ak + 1][ar] = av.y;
        As[ak + 2][ar] = av.z; As[ak + 3][ar] = av.w;
        if (tid < 128) {
            float4 bv = *(const float4*)(Bptr + k0);
            Bs[bks + 0][bnr] = bv.x; Bs[bks + 1][bnr] = bv.y;
            Bs[bks + 2][bnr] = bv.z; Bs[bks + 3][bnr] = bv.w;
        }
        __syncthreads();
        #pragma unroll
        for (int kk = 0; kk < GBK; kk++) {
            float4 a0 = *(const float4*)&As[kk][tr * 8];
            float4 a1 = *(const float4*)&As[kk][tr * 8 + 4];
            float4 b0 = *(const float4*)&Bs[kk][tc * 4];
            float a[8] = {a0.x, a0.y, a0.z, a0.w, a1.x, a1.y, a1.z, a1.w};
            float b[4] = {b0.x, b0.y, b0.z, b0.w};
            #pragma unroll
            for (int i = 0; i < 8; i++)
                #pragma unroll
                for (int j = 0; j < 4; j++) acc[i][j] = fmaf(a[i], b[j], acc[i][j]);
        }
        __syncthreads();
    }

    #pragma unroll
    for (int i = 0; i < 8; i++) {
        long off = (long)(row0 + tr * 8 + i) * ldc + col0 + tc * 4;
        *(float4*)(C + off) = make_float4(acc[i][0], acc[i][1], acc[i][2], acc[i][3]);
    }
}

// ---------------------------------------------------------------------------
// Pointwise / row kernels
// ---------------------------------------------------------------------------
__global__ void embed_k(const int* __restrict__ tokens, const float* __restrict__ emb,
                        float* __restrict__ y) {
    int r = blockIdx.x;
    int tok = tokens[r];
    const float4* src = (const float4*)(emb + (long)tok * Dc);
    float4* dst = (float4*)(y + (long)r * Dc);
    for (int i = threadIdx.x; i < Dc / 4; i += blockDim.x) dst[i] = src[i];
}

__global__ void rmsnorm_k(const float* __restrict__ in, const float* __restrict__ w,
                          float* __restrict__ out) {
    long base = (long)blockIdx.x * Dc;
    float s = 0.0f;
    for (int i = threadIdx.x; i < Dc; i += blockDim.x) {
        float v = in[base + i];
        s += v * v;
    }
    s = blockReduceSum(s);
    float inv = 1.0f / sqrtf(s * (1.0f / Dc) + 1e-6f);
    for (int i = threadIdx.x; i < Dc; i += blockDim.x)
        out[base + i] = in[base + i] * inv * w[i];
}

// RoPE on q and k; q additionally scaled by 1/sqrt(Dh) = 1/8.
__global__ void rope_k(float* __restrict__ q, float* __restrict__ k) {
    int idx = blockIdx.x * blockDim.x + threadIdx.x;   // over B*L*H*32
    if (idx >= Bc * Lc * Hc * 32) return;
    int i = idx & 31;
    int rest = idx >> 5;
    int h = rest & (Hc - 1);
    int rl = rest >> 4;            // b*L + l
    int l = rl & (Lc - 1);
    float ts = powf(10000.0f, (float)i * (1.0f / 32.0f));
    float ang = (float)l / ts;
    float sn = sinf(ang), cs = cosf(ang);
    long base = (long)rl * Dc + h * DHc + i;
    float q1 = q[base], q2 = q[base + 32];
    q[base]      = (q1 * cs - q2 * sn) * 0.125f;
    q[base + 32] = (q2 * cs + q1 * sn) * 0.125f;
    float k1 = k[base], k2 = k[base + 32];
    k[base]      = k1 * cs - k2 * sn;
    k[base + 32] = k2 * cs + k1 * sn;
}

__global__ void softmax_causal(float* __restrict__ att) {
    int qi = blockIdx.x;
    long base = ((long)blockIdx.y * Lc + qi) * Lc;
    float mx = -FLT_MAX;
    for (int kk = threadIdx.x; kk <= qi; kk += blockDim.x)
        mx = fmaxf(mx, att[base + kk]);
    mx = blockReduceMax(mx);
    float s = 0.0f;
    for (int kk = threadIdx.x; kk <= qi; kk += blockDim.x) {
        float e = expf(att[base + kk] - mx);
        att[base + kk] = e;
        s += e;
    }
    s = blockReduceSum(s);
    float inv = 1.0f / s;
    for (int kk = threadIdx.x; kk < Lc; kk += blockDim.x)
        att[base + kk] = (kk <= qi) ? att[base + kk] * inv : 0.0f;
}

__global__ void swishmul_k(float* __restrict__ g, const float* __restrict__ p) {
    int idx = blockIdx.x * blockDim.x + threadIdx.x;
    if (idx >= Bc * Lc * Fc) return;
    float gv = g[idx];
    float sg = 1.0f / (1.0f + expf(-gv));
    g[idx] = gv * sg * p[idx];
}

// ---------------------------------------------------------------------------
// Host side
// ---------------------------------------------------------------------------
static void launch_nn(const float* A, const float* B, float* C, const float* R,
                      int M, int N, int K, int lda, int ldb, int ldc,
                      int batches = 1, int bH = 1,
                      long sAb = 0, long sAh = 0, long sBb = 0, long sBh = 0,
                      long sCb = 0, long sCh = 0) {
    dim3 grid(N / GBN, M / GBM, batches);
    sgemm_nn<<<grid, 256>>>(A, B, C, R, K, lda, ldb, ldc,
                            bH, sAb, sAh, sBb, sBh, sCb, sCh);
}

static void launch_nt(const float* A, const float* B, float* C,
                      int M, int N, int K, int lda, int ldb, int ldc,
                      int batches, int bH,
                      long sAb, long sAh, long sBb, long sBh,
                      long sCb, long sCh) {
    dim3 grid(N / GBN, M / GBM, batches);
    sgemm_nt<<<grid, 256>>>(A, B, C, K, lda, ldb, ldc,
                            bH, sAb, sAh, sBb, sBh, sCb, sCh);
}

extern "C" void kernel_launch(void* const* d_in, const int* in_sizes, int n_in,
                              void* d_out, int out_size) {
    const int*   tokens = (const int*)d_in[0];
    const float* embed  = (const float*)d_in[1];
    const float* ln1    = (const float*)d_in[2];
    const float* Wq     = (const float*)d_in[3];
    const float* Wk     = (const float*)d_in[4];
    const float* Wv     = (const float*)d_in[5];
    const float* Wo     = (const float*)d_in[6];
    const float* ln2    = (const float*)d_in[7];
    const float* Wg     = (const float*)d_in[8];
    const float* Wp     = (const float*)d_in[9];
    const float* Wd     = (const float*)d_in[10];
    const float* out_ln = (const float*)d_in[11];
    const float* head   = (const float*)d_in[12];

    float *y, *x, *q, *k, *v, *t, *att, *gg, *pp;
    cudaGetSymbolAddress((void**)&y,   g_y);
    cudaGetSymbolAddress((void**)&x,   g_x);
    cudaGetSymbolAddress((void**)&q,   g_q);
    cudaGetSymbolAddress((void**)&k,   g_k);
    cudaGetSymbolAddress((void**)&v,   g_v);
    cudaGetSymbolAddress((void**)&t,   g_t);
    cudaGetSymbolAddress((void**)&att, g_att);
    cudaGetSymbolAddress((void**)&gg,  g_g);
    cudaGetSymbolAddress((void**)&pp,  g_p);

    const int M = Bc * Lc;                 // 2048 rows of activations

    embed_k<<<M, 256>>>(tokens, embed, y);

    for (int layer = 0; layer < NLAYER; layer++) {
        const float* ln1l = ln1 + (long)layer * Dc;
        const float* ln2l = ln2 + (long)layer * Dc;
        const float* Wql  = Wq  + (long)layer * Dc * Dc;
        const float* Wkl  = Wk  + (long)layer * Dc * Dc;
        const float* Wvl  = Wv  + (long)layer * Dc * Dc;
        const float* Wol  = Wo  + (long)layer * Dc * Dc;
        const float* Wgl  = Wg  + (long)layer * Dc * Fc;
        const float* Wpl  = Wp  + (long)layer * Dc * Fc;
        const float* Wdl  = Wd  + (long)layer * Fc * Dc;

        // x = rmsnorm(y, ln1)
        rmsnorm_k<<<M, 256>>>(y, ln1l, x);

        // q,k,v projections
        launch_nn(x, Wql, q, nullptr, M, Dc, Dc, Dc, Dc, Dc);
        launch_nn(x, Wkl, k, nullptr, M, Dc, Dc, Dc, Dc, Dc);
        launch_nn(x, Wvl, v, nullptr, M, Dc, Dc, Dc, Dc, Dc);

        // RoPE (+ q scale)
        rope_k<<<(Bc * Lc * Hc * 32 + 255) / 256, 256>>>(q, k);

        // scores: att[b,h,qi,ki] = q[b,qi,h,:] . k[b,ki,h,:]
        launch_nt(q, k, att, Lc, Lc, DHc, Dc, Dc, Lc,
                  Bc * Hc, Hc,
                  (long)Lc * Dc, DHc,          // A strides (b, h)
                  (long)Lc * Dc, DHc,          // B strides
                  (long)Hc * Lc * Lc, (long)Lc * Lc);

        // causal softmax rows
        softmax_causal<<<dim3(Lc, Bc * Hc), 256>>>(att);

        // out: t[b,qi,h,:] = att[b,h,qi,:] @ v[b,:,h,:]
        launch_nn(att, v, t, nullptr, Lc, DHc, Lc, Lc, Dc, Dc,
                  Bc * Hc, Hc,
                  (long)Hc * Lc * Lc, (long)Lc * Lc,
                  (long)Lc * Dc, DHc,
                  (long)Lc * Dc, DHc);

        // y = y + t @ Wo   (residual fused)
        launch_nn(t, Wol, y, y, M, Dc, Dc, Dc, Dc, Dc);

        // FFN
        rmsnorm_k<<<M, 256>>>(y, ln2l, x);
        launch_nn(x, Wgl, gg, nullptr, M, Fc, Dc, Dc, Fc, Fc);
        launch_nn(x, Wpl, pp, nullptr, M, Fc, Dc, Dc, Fc, Fc);
        swishmul_k<<<(Bc * Lc * Fc + 255) / 256, 256>>>(gg, pp);
        // y = y + h @ Wd
        launch_nn(gg, Wdl, y, y, M, Dc, Fc, Fc, Dc, Dc);
    }

    // final norm + head
    rmsnorm_k<<<M, 256>>>(y, out_ln, x);
    launch_nn(x, head, (float*)d_out, nullptr, M, Vc, Dc, Dc, Vc, Vc);
}

// round 2
// speedup vs baseline: 1.0036x; 1.0036x over previous
#include <cuda_runtime.h>
#include <math.h>
#include <float.h>

// Problem constants
#define Bc 2
#define Lc 1024
#define Dc 1024
#define Hc 16
#define NLAYER 8
#define Vc 32000
#define Fc 4096
#define DHc 64

// ---------------------------------------------------------------------------
// Device-global scratch (no runtime allocation allowed)
// ---------------------------------------------------------------------------
__device__ float g_y[Bc * Lc * Dc];      // residual stream
__device__ float g_x[Bc * Lc * Dc];      // rmsnorm output
__device__ float g_q[Bc * Lc * Dc];
__device__ float g_k[Bc * Lc * Dc];
__device__ float g_v[Bc * Lc * Dc];
__device__ float g_t[Bc * Lc * Dc];      // attention output (pre-Wo)
__device__ float g_att[Bc * Hc * Lc * Lc];  // attention scores/probs (128 MB)
__device__ float g_g[Bc * Lc * Fc];      // FFN gate / fused hidden
__device__ float g_p[Bc * Lc * Fc];      // FFN proj

// ---------------------------------------------------------------------------
// Block reductions
// ---------------------------------------------------------------------------
__device__ __forceinline__ float blockReduceSum(float v) {
    __shared__ float sh[33];
    int lane = threadIdx.x & 31, wid = threadIdx.x >> 5;
    #pragma unroll
    for (int o = 16; o > 0; o >>= 1) v += __shfl_down_sync(0xffffffffu, v, o);
    if (lane == 0) sh[wid] = v;
    __syncthreads();
    v = (threadIdx.x < (blockDim.x >> 5)) ? sh[lane] : 0.0f;
    if (wid == 0) {
        #pragma unroll
        for (int o = 16; o > 0; o >>= 1) v += __shfl_down_sync(0xffffffffu, v, o);
        if (lane == 0) sh[32] = v;
    }
    __syncthreads();
    return sh[32];
}

__device__ __forceinline__ float blockReduceMax(float v) {
    __shared__ float sh[33];
    int lane = threadIdx.x & 31, wid = threadIdx.x >> 5;
    #pragma unroll
    for (int o = 16; o > 0; o >>= 1) v = fmaxf(v, __shfl_down_sync(0xffffffffu, v, o));
    if (lane == 0) sh[wid] = v;
    __syncthreads();
    v = (threadIdx.x < (blockDim.x >> 5)) ? sh[lane] : -FLT_MAX;
    if (wid == 0) {
        #pragma unroll
        for (int o = 16; o > 0; o >>= 1) v = fmaxf(v, __shfl_down_sync(0xffffffffu, v, o));
        if (lane == 0) sh[32] = v;
    }
    __syncthreads();
    return sh[32];
}

// ---------------------------------------------------------------------------
// Tiled SGEMM: C[M,N] = A[M,K] @ B[K,N]  (+ optional residual R, same layout as C)
// BM=128, BN=64, BK=8, 256 threads, 8x4 per thread.
// Batched via blockIdx.z decomposed as (zb, zh) with zh = z % bH.
// ---------------------------------------------------------------------------
#define GBM 128
#define GBN 64
#define GBK 8

__global__ __launch_bounds__(256) void sgemm_nn(
    const float* __restrict__ A, const float* __restrict__ B,
    float* __restrict__ C, const float* __restrict__ R,
    int K, int lda, int ldb, int ldc,
    int bH, long sAb, long sAh, long sBb, long sBh, long sCb, long sCh)
{
    int z = blockIdx.z;
    int zb = z / bH, zh = z - zb * bH;
    A += (long)zb * sAb + (long)zh * sAh;
    B += (long)zb * sBb + (long)zh * sBh;
    long coff = (long)zb * sCb + (long)zh * sCh;
    C += coff;
    if (R) R += coff;

    __shared__ float As[GBK][GBM];
    __shared__ float Bs[GBK][GBN];

    int tid = threadIdx.x;
    int row0 = blockIdx.y * GBM, col0 = blockIdx.x * GBN;

    int ar = tid >> 1;              // 0..127
    int ak = (tid & 1) << 2;        // 0 or 4
    int bk = tid >> 4;              // valid when tid<128: 0..7
    int bn = (tid & 15) << 2;       // 0..60
    int tr = tid >> 4, tc = tid & 15;

    float acc[8][4];
    #pragma unroll
    for (int i = 0; i < 8; i++)
        #pragma unroll
        for (int j = 0; j < 4; j++) acc[i][j] = 0.0f;

    const float* Aptr = A + (long)(row0 + ar) * lda + ak;
    const float* Bptr = B + (long)bk * ldb + col0 + bn;

    for (int k0 = 0; k0 < K; k0 += GBK) {
        float4 av = *(const float4*)(Aptr + k0);
        As[ak + 0][ar] = av.x; As[ak + 1][ar] = av.y;
        As[ak + 2][ar] = av.z; As[ak + 3][ar] = av.w;
        if (tid < 128) {
            float4 bv = *(const float4*)(Bptr + (long)k0 * ldb);
            *(float4*)&Bs[bk][bn] = bv;
        }
        __syncthreads();
        #pragma unroll
        for (int kk = 0; kk < GBK; kk++) {
            float4 a0 = *(const float4*)&As[kk][tr * 8];
            float4 a1 = *(const float4*)&As[kk][tr * 8 + 4];
            float4 b0 = *(const float4*)&Bs[kk][tc * 4];
            float a[8] = {a0.x, a0.y, a0.z, a0.w, a1.x, a1.y, a1.z, a1.w};
            float b[4] = {b0.x, b0.y, b0.z, b0.w};
            #pragma unroll
            for (int i = 0; i < 8; i++)
                #pragma unroll
                for (int j = 0; j < 4; j++) acc[i][j] = fmaf(a[i], b[j], acc[i][j]);
        }
        __syncthreads();
    }

    #pragma unroll
    for (int i = 0; i < 8; i++) {
        long off = (long)(row0 + tr * 8 + i) * ldc + col0 + tc * 4;
        float4 res = make_float4(acc[i][0], acc[i][1], acc[i][2], acc[i][3]);
        if (R) {
            float4 rv = *(const float4*)(R + off);
            res.x += rv.x; res.y += rv.y; res.z += rv.z; res.w += rv.w;
        }
        *(float4*)(C + off) = res;
    }
}

// NT variant: C[M,N] = A[M,K] @ B[N,K]^T  (B row-major N x K)
__global__ __launch_bounds__(256) void sgemm_nt(
    const float* __restrict__ A, const float* __restrict__ B,
    float* __restrict__ C,
    int K, int lda, int ldb, int ldc,
    int bH, long sAb, long sAh, long sBb, long sBh, long sCb, long sCh)
{
    int z = blockIdx.z;
    int zb = z / bH, zh = z - zb * bH;
    A += (long)zb * sAb + (long)zh * sAh;
    B += (long)zb * sBb + (long)zh * sBh;
    C += (long)zb * sCb + (long)zh * sCh;

    __shared__ float As[GBK][GBM];
    __shared__ float Bs[GBK][GBN];

    int tid = threadIdx.x;
    int row0 = blockIdx.y * GBM, col0 = blockIdx.x * GBN;

    int ar = tid >> 1;
    int ak = (tid & 1) << 2;
    int bnr = tid >> 1;             // valid when tid<128: 0..63
    int bks = (tid & 1) << 2;
    int tr = tid >> 4, tc = tid & 15;

    float acc[8][4];
    #pragma unroll
    for (int i = 0; i < 8; i++)
        #pragma unroll
        for (int j = 0; j < 4; j++) acc[i][j] = 0.0f;

    const float* Aptr = A + (long)(row0 + ar) * lda + ak;
    const float* Bptr = B + (long)(col0 + (bnr & 63)) * ldb + bks;

    for (int k0 = 0; k0 < K; k0 += GBK) {
        float4 av = *(const float4*)(Aptr + k0);
        As[ak + 0][ar] = av.x; As[ak + 1][ar] = av.y;
        As[ak + 2][ar] = av.z; As[ak + 3][ar] = av.w;
        if (tid < 128) {
            float4 bv = *(const float4*)(Bptr + k0);
            Bs[bks + 0][bnr] = bv.x; Bs[bks + 1][bnr] = bv.y;
            Bs[bks + 2][bnr] = bv.z; Bs[bks + 3][bnr] = bv.w;
        }
        __syncthreads();
        #pragma unroll
        for (int kk = 0; kk < GBK; kk++) {
            float4 a0 = *(const float4*)&As[kk][tr * 8];
            float4 a1 = *(const float4*)&As[kk][tr * 8 + 4];
            float4 b0 = *(const float4*)&Bs[kk][tc * 4];
            float a[8] = {a0.x, a0.y, a0.z, a0.w, a1.x, a1.y, a1.z, a1.w};
            float b[4] = {b0.x, b0.y, b0.z, b0.w};
            #pragma unroll
            for (int i = 0; i < 8; i++)
                #pragma unroll
                for (int j = 0; j < 4; j++) acc[i][j] = fmaf(a[i], b[j], acc[i][j]);
        }
        __syncthreads();
    }

    #pragma unroll
    for (int i = 0; i < 8; i++) {
        long off = (long)(row0 + tr * 8 + i) * ldc + col0 + tc * 4;
        *(float4*)(C + off) = make_float4(acc[i][0], acc[i][1], acc[i][2], acc[i][3]);
    }
}

// ---------------------------------------------------------------------------
// Pointwise / row kernels
// ---------------------------------------------------------------------------
__global__ void embed_k(const int* __restrict__ tokens, const float* __restrict__ emb,
                        float* __restrict__ y) {
    int r = blockIdx.x;
    int tok = tokens[r];
    const float4* src = (const float4*)(emb + (long)tok * Dc);
    float4* dst = (float4*)(y + (long)r * Dc);
    for (int i = threadIdx.x; i < Dc / 4; i += blockDim.x) dst[i] = src[i];
}

__global__ void rmsnorm_k(const float* __restrict__ in, const float* __restrict__ w,
                          float* __restrict__ out) {
    long base = (long)blockIdx.x * Dc;
    float s = 0.0f;
    for (int i = threadIdx.x; i < Dc; i += blockDim.x) {
        float v = in[base + i];
        s += v * v;
    }
    s = blockReduceSum(s);
    float inv = 1.0f / sqrtf(s * (1.0f / Dc) + 1e-6f);
    for (int i = threadIdx.x; i < Dc; i += blockDim.x)
        out[base + i] = in[base + i] * inv * w[i];
}

// RoPE on q and k; q additionally scaled by 1/sqrt(Dh) = 1/8.
__global__ void rope_k(float* __restrict__ q, float* __restrict__ k) {
    int idx = blockIdx.x * blockDim.x + threadIdx.x;   // over B*L*H*32
    if (idx >= Bc * Lc * Hc * 32) return;
    int i = idx & 31;
    int rest = idx >> 5;
    int h = rest & (Hc - 1);
    int rl = rest >> 4;            // b*L + l
    int l = rl & (Lc - 1);
    float ts = powf(10000.0f, (float)i * (1.0f / 32.0f));
    float ang = (float)l / ts;
    float sn = sinf(ang), cs = cosf(ang);
    long base = (long)rl * Dc + h * DHc + i;
    float q1 = q[base], q2 = q[base + 32];
    q[base]      = (q1 * cs - q2 * sn) * 0.125f;
    q[base + 32] = (q2 * cs + q1 * sn) * 0.125f;
    float k1 = k[base], k2 = k[base + 32];
    k[base]      = k1 * cs - k2 * sn;
    k[base + 32] = k2 * cs + k1 * sn;
}

__global__ void softmax_causal(float* __restrict__ att) {
    int qi = blockIdx.x;
    long base = ((long)blockIdx.y * Lc + qi) * Lc;
    float mx = -FLT_MAX;
    for (int kk = threadIdx.x; kk <= qi; kk += blockDim.x)
        mx = fmaxf(mx, att[base + kk]);
    mx = blockReduceMax(mx);
    float s = 0.0f;
    for (int kk = threadIdx.x; kk <= qi; kk += blockDim.x) {
        float e = expf(att[base + kk] - mx);
        att[base + kk] = e;
        s += e;
    }
    s = blockReduceSum(s);
    float inv = 1.0f / s;
    for (int kk = threadIdx.x; kk < Lc; kk += blockDim.x)
        att[base + kk] = (kk <= qi) ? att[base + kk] * inv : 0.0f;
}

__global__ void swishmul_k(float* __restrict__ g, const float* __restrict__ p) {
    int idx = blockIdx.x * blockDim.x + threadIdx.x;
    if (idx >= Bc * Lc * Fc) return;
    float gv = g[idx];
    float sg = 1.0f / (1.0f + expf(-gv));
    g[idx] = gv * sg * p[idx];
}

// ---------------------------------------------------------------------------
// Host side
// ---------------------------------------------------------------------------
static void launch_nn(const float* A, const float* B, float* C, const float* R,
                      int M, int N, int K, int lda, int ldb, int ldc,
                      int batches = 1, int bH = 1,
                      long sAb = 0, long sAh = 0, long sBb = 0, long sBh = 0,
                      long sCb = 0, long sCh = 0) {
    dim3 grid(N / GBN, M / GBM, batches);
    sgemm_nn<<<grid, 256>>>(A, B, C, R, K, lda, ldb, ldc,
                            bH, sAb, sAh, sBb, sBh, sCb, sCh);
}

static void launch_nt(const float* A, const float* B, float* C,
                      int M, int N, int K, int lda, int ldb, int ldc,
                      int batches, int bH,
                      long sAb, long sAh, long sBb, long sBh,
                      long sCb, long sCh) {
    dim3 grid(N / GBN, M / GBM, batches);
    sgemm_nt<<<grid, 256>>>(A, B, C, K, lda, ldb, ldc,
                            bH, sAb, sAh, sBb, sBh, sCb, sCh);
}

extern "C" void kernel_launch(void* const* d_in, const int* in_sizes, int n_in,
                              void* d_out, int out_size) {
    const int*   tokens = (const int*)d_in[0];
    const float* embed  = (const float*)d_in[1];
    const float* ln1    = (const float*)d_in[2];
    const float* Wq     = (const float*)d_in[3];
    const float* Wk     = (const float*)d_in[4];
    const float* Wv     = (const float*)d_in[5];
    const float* Wo     = (const float*)d_in[6];
    const float* ln2    = (const float*)d_in[7];
    const float* Wg     = (const float*)d_in[8];
    const float* Wp     = (const float*)d_in[9];
    const float* Wd     = (const float*)d_in[10];
    const float* out_ln = (const float*)d_in[11];
    const float* head   = (const float*)d_in[12];

    float *y, *x, *q, *k, *v, *t, *att, *gg, *pp;
    cudaGetSymbolAddress((void**)&y,   g_y);
    cudaGetSymbolAddress((void**)&x,   g_x);
    cudaGetSymbolAddress((void**)&q,   g_q);
    cudaGetSymbolAddress((void**)&k,   g_k);
    cudaGetSymbolAddress((void**)&v,   g_v);
    cudaGetSymbolAddress((void**)&t,   g_t);
    cudaGetSymbolAddress((void**)&att, g_att);
    cudaGetSymbolAddress((void**)&gg,  g_g);
    cudaGetSymbolAddress((void**)&pp,  g_p);

    const int M = Bc * Lc;                 // 2048 rows of activations

    embed_k<<<M, 256>>>(tokens, embed, y);

    for (int layer = 0; layer < NLAYER; layer++) {
        const float* ln1l = ln1 + (long)layer * Dc;
        const float* ln2l = ln2 + (long)layer * Dc;
        const float* Wql  = Wq  + (long)layer * Dc * Dc;
        const float* Wkl  = Wk  + (long)layer * Dc * Dc;
        const float* Wvl  = Wv  + (long)layer * Dc * Dc;
        const float* Wol  = Wo  + (long)layer * Dc * Dc;
        const float* Wgl  = Wg  + (long)layer * Dc * Fc;
        const float* Wpl  = Wp  + (long)layer * Dc * Fc;
        const float* Wdl  = Wd  + (long)layer * Fc * Dc;

        // x = rmsnorm(y, ln1)
        rmsnorm_k<<<M, 256>>>(y, ln1l, x);

        // q,k,v projections
        launch_nn(x, Wql, q, nullptr, M, Dc, Dc, Dc, Dc, Dc);
        launch_nn(x, Wkl, k, nullptr, M, Dc, Dc, Dc, Dc, Dc);
        launch_nn(x, Wvl, v, nullptr, M, Dc, Dc, Dc, Dc, Dc);

        // RoPE (+ q scale)
        rope_k<<<(Bc * Lc * Hc * 32 + 255) / 256, 256>>>(q, k);

        // scores: att[b,h,qi,ki] = q[b,qi,h,:] . k[b,ki,h,:]
        launch_nt(q, k, att, Lc, Lc, DHc, Dc, Dc, Lc,
                  Bc * Hc, Hc,
                  (long)Lc * Dc, DHc,          // A strides (b, h)
                  (long)Lc * Dc, DHc,          // B strides
                  (long)Hc * Lc * Lc, (long)Lc * Lc);

        // causal softmax rows
        softmax_causal<<<dim3(Lc, Bc * Hc), 256>>>(att);

        // out: t[b,qi,h,:] = att[b,h,qi,:] @ v[b,:,h,:]
        launch_nn(att, v, t, nullptr, Lc, DHc, Lc, Lc, Dc, Dc,
                  Bc * Hc, Hc,
                  (long)Hc * Lc * Lc, (long)Lc * Lc,
                  (long)Lc * Dc, DHc,
                  (long)Lc * Dc, DHc);

        // y = y + t @ Wo   (residual fused)
        launch_nn(t, Wol, y, y, M, Dc, Dc, Dc, Dc, Dc);

        // FFN
        rmsnorm_k<<<M, 256>>>(y, ln2l, x);
        launch_nn(x, Wgl, gg, nullptr, M, Fc, Dc, Dc, Fc, Fc);
        launch_nn(x, Wpl, pp, nullptr, M, Fc, Dc, Dc, Fc, Fc);
        swishmul_k<<<(Bc * Lc * Fc + 255) / 256, 256>>>(gg, pp);
        // y = y + h @ Wd
        launch_nn(gg, Wdl, y, y, M, Dc, Fc, Fc, Dc, Dc);
    }

    // final norm + head
    rmsnorm_k<<<M, 256>>>(y, out_ln, x);
    launch_nn(x, head, (float*)d_out, nullptr, M, Vc, Dc, Dc, Vc, Vc);
}

// round 4
// speedup vs baseline: 1.9762x; 1.9692x over previous
#include <cuda_runtime.h>
#include <cuda_bf16.h>
#include <mma.h>
#include <math.h>
#include <float.h>
#include <stdint.h>

using namespace nvcuda;

#define Bc 2
#define Lc 1024
#define Dc 1024
#define Hc 16
#define NL 8
#define Vc 32000
#define Fc 4096
#define DHc 64

// ---------------------------------------------------------------------------
// Device-global scratch
// ---------------------------------------------------------------------------
__device__ float g_y[Bc*Lc*Dc];
__device__ float g_q[Bc*Lc*Dc];
__device__ float g_k[Bc*Lc*Dc];
__device__ float g_v[Bc*Lc*Dc];
__device__ float g_att[Bc*Hc*Lc*Lc];
__device__ float g_gf[Bc*Lc*Fc];
__device__ float g_pf[Bc*Lc*Fc];
// packed (u32 = bf16 hi | bf16 lo << 16)
__device__ uint32_t g_x2[Bc*Lc*Dc];
__device__ uint32_t g_q2[Bc*Lc*Dc];
__device__ uint32_t g_k2[Bc*Lc*Dc];
__device__ uint32_t g_vt2[Bc*Hc*DHc*Lc];
__device__ uint32_t g_t2[Bc*Lc*Dc];
__device__ uint32_t g_p2[Bc*Hc*Lc*Lc];
__device__ uint32_t g_g2[Bc*Lc*Fc];
__device__ uint32_t g_w2[166985728];   // transposed+packed weights + head

__device__ __forceinline__ uint32_t packf(float v) {
    __nv_bfloat16 h = __float2bfloat16(v);
    float hf = __bfloat162float(h);
    __nv_bfloat16 l = __float2bfloat16(v - hf);
    return (uint32_t)__bfloat16_as_ushort(h) | ((uint32_t)__bfloat16_as_ushort(l) << 16);
}

// ---------------------------------------------------------------------------
// Block reductions (blockDim.x == 256)
// ---------------------------------------------------------------------------
__device__ __forceinline__ float blockReduceSum(float v) {
    __shared__ float sh[33];
    int lane = threadIdx.x & 31, wid = threadIdx.x >> 5;
    #pragma unroll
    for (int o = 16; o > 0; o >>= 1) v += __shfl_down_sync(0xffffffffu, v, o);
    if (lane == 0) sh[wid] = v;
    __syncthreads();
    v = (threadIdx.x < 8) ? sh[lane] : 0.0f;
    if (wid == 0) {
        #pragma unroll
        for (int o = 4; o > 0; o >>= 1) v += __shfl_down_sync(0xffffffffu, v, o);
        if (lane == 0) sh[32] = v;
    }
    __syncthreads();
    return sh[32];
}
__device__ __forceinline__ float blockReduceMax(float v) {
    __shared__ float sh[33];
    int lane = threadIdx.x & 31, wid = threadIdx.x >> 5;
    #pragma unroll
    for (int o = 16; o > 0; o >>= 1) v = fmaxf(v, __shfl_down_sync(0xffffffffu, v, o));
    if (lane == 0) sh[wid] = v;
    __syncthreads();
    v = (threadIdx.x < 8) ? sh[lane] : -FLT_MAX;
    if (wid == 0) {
        #pragma unroll
        for (int o = 4; o > 0; o >>= 1) v = fmaxf(v, __shfl_down_sync(0xffffffffu, v, o));
        if (lane == 0) sh[32] = v;
    }
    __syncthreads();
    return sh[32];
}

// ---------------------------------------------------------------------------
// WMMA GEMM: D[M,N] = A[M,K] @ B[N,K]^T, bf16x3 split (hi*hi+hi*lo+lo*hi),
// fp32 accum. A, B: packed u32 (hi | lo<<16), K-major rows.
// BM=128, BN template {128,64}, BK=32. 256 threads = 8 warps (4 M x 2 N).
// flags: bit1 = causal tile skip (scores), bit2 = K clip to row0+128 (AV).
// Cp != null -> packed u32 output; else fp32 C (residual R folded into acc init).
// ---------------------------------------------------------------------------
#define LDS_ 40   // smem row stride in bf16 (32 + 8 pad)

template<int BN>
__global__ __launch_bounds__(256) void gemm_mma(
    const uint32_t* __restrict__ A, const uint32_t* __restrict__ B,
    float* __restrict__ C, uint32_t* __restrict__ Cp, const float* __restrict__ R,
    int K, int lda, int ldb, int ldc, int bH,
    long sAb, long sAh, long sBb, long sBh, long sCb, long sCh, int flags)
{
    const int BM = 128, BK = 32;
    const int NT = BN / 32;          // B tiles per warp (4 or 2)
    const int WN = BN / 2;           // warp N span
    const int NA4 = 4;               // A uint4 loads per thread per chunk
    const int NB4 = BN * 8 / 256;    // B uint4 loads per thread per chunk

    int row0 = blockIdx.y * BM, col0 = blockIdx.x * BN;
    if ((flags & 2) && col0 >= row0 + BM) return;
    if (flags & 4) { int kc = row0 + BM; if (kc < K) K = kc; }
    int z = blockIdx.z, zb = z / bH, zh = z - zb * bH;
    A += (long)zb * sAb + (long)zh * sAh;
    B += (long)zb * sBb + (long)zh * sBh;
    long coff = (long)zb * sCb + (long)zh * sCh;

    extern __shared__ char smraw[];
    const int ASZ = BM * LDS_;          // bf16 elems per A plane
    const int BSZ = BN * LDS_;
    const int STAGE = 2 * ASZ + 2 * BSZ;

    int tid = threadIdx.x, wid = tid >> 5, lane = tid & 31;
    int wm = wid & 3, wn = wid >> 2;

    wmma::fragment<wmma::accumulator, 16, 16, 16, float> acc[2][NT];
    if (R) {
        const float* Rb = R + coff;
        #pragma unroll
        for (int i = 0; i < 2; i++)
            #pragma unroll
            for (int j = 0; j < NT; j++)
                wmma::load_matrix_sync(acc[i][j],
                    Rb + (long)(row0 + wm * 32 + i * 16) * ldc + col0 + wn * WN + j * 16,
                    ldc, wmma::mem_row_major);
    } else {
        #pragma unroll
        for (int i = 0; i < 2; i++)
            #pragma unroll
            for (int j = 0; j < NT; j++)
                wmma::fill_fragment(acc[i][j], 0.0f);
    }

    int lda4 = lda >> 2, ldb4 = ldb >> 2;
    const uint4* Ag = (const uint4*)A + (long)row0 * lda4;
    const uint4* Bg = (const uint4*)B + (long)col0 * ldb4;
    int NC = K >> 5;

    uint4 pa[NA4], pb[NB4];

    // ---- prologue: chunk 0 ----
    {
        int kc4 = 0;
        #pragma unroll
        for (int i = 0; i < NA4; i++) {
            int lin = tid + i * 256, r = lin >> 3, g = lin & 7;
            pa[i] = Ag[(long)r * lda4 + kc4 + g];
        }
        #pragma unroll
        for (int i = 0; i < NB4; i++) {
            int lin = tid + i * 256, r = lin >> 3, g = lin & 7;
            pb[i] = Bg[(long)r * ldb4 + kc4 + g];
        }
    }
    {
        __nv_bfloat16* st = (__nv_bfloat16*)smraw;
        #pragma unroll
        for (int i = 0; i < NA4; i++) {
            int lin = tid + i * 256, r = lin >> 3, g = lin & 7;
            uint4 p = pa[i];
            uint2 hv = make_uint2(__byte_perm(p.x, p.y, 0x5410), __byte_perm(p.z, p.w, 0x5410));
            uint2 lv = make_uint2(__byte_perm(p.x, p.y, 0x7632), __byte_perm(p.z, p.w, 0x7632));
            *(uint2*)(st + r * LDS_ + g * 4) = hv;
            *(uint2*)(st + ASZ + r * LDS_ + g * 4) = lv;
        }
        #pragma unroll
        for (int i = 0; i < NB4; i++) {
            int lin = tid + i * 256, r = lin >> 3, g = lin & 7;
            uint4 p = pb[i];
            uint2 hv = make_uint2(__byte_perm(p.x, p.y, 0x5410), __byte_perm(p.z, p.w, 0x5410));
            uint2 lv = make_uint2(__byte_perm(p.x, p.y, 0x7632), __byte_perm(p.z, p.w, 0x7632));
            *(uint2*)(st + 2 * ASZ + r * LDS_ + g * 4) = hv;
            *(uint2*)(st + 2 * ASZ + BSZ + r * LDS_ + g * 4) = lv;
        }
    }
    __syncthreads();

    for (int c = 0; c < NC; c++) {
        // prefetch next chunk into registers (overlaps with compute)
        if (c + 1 < NC) {
            int kc4 = (c + 1) * 8;
            #pragma unroll
            for (int i = 0; i < NA4; i++) {
                int lin = tid + i * 256, r = lin >> 3, g = lin & 7;
                pa[i] = Ag[(long)r * lda4 + kc4 + g];
            }
            #pragma unroll
            for (int i = 0; i < NB4; i++) {
                int lin = tid + i * 256, r = lin >> 3, g = lin & 7;
                pb[i] = Bg[(long)r * ldb4 + kc4 + g];
            }
        }

        // compute from stage c&1
        {
            const __nv_bfloat16* base = (const __nv_bfloat16*)smraw + (c & 1) * STAGE;
            const __nv_bfloat16* Ah = base;
            const __nv_bfloat16* Al = base + ASZ;
            const __nv_bfloat16* Bh = base + 2 * ASZ;
            const __nv_bfloat16* Bl = base + 2 * ASZ + BSZ;
            #pragma unroll
            for (int ks = 0; ks < 2; ks++) {
                int k0 = ks * 16;
                wmma::fragment<wmma::matrix_a, 16, 16, 16, __nv_bfloat16, wmma::row_major> fah[2], fal[2];
                #pragma unroll
                for (int i = 0; i < 2; i++) {
                    wmma::load_matrix_sync(fah[i], Ah + (wm * 32 + i * 16) * LDS_ + k0, LDS_);
                    wmma::load_matrix_sync(fal[i], Al + (wm * 32 + i * 16) * LDS_ + k0, LDS_);
                }
                #pragma unroll
                for (int j = 0; j < NT; j++) {
                    wmma::fragment<wmma::matrix_b, 16, 16, 16, __nv_bfloat16, wmma::col_major> fbh, fbl;
                    wmma::load_matrix_sync(fbh, Bh + (wn * WN + j * 16) * LDS_ + k0, LDS_);
                    wmma::load_matrix_sync(fbl, Bl + (wn * WN + j * 16) * LDS_ + k0, LDS_);
                    #pragma unroll
                    for (int i = 0; i < 2; i++) {
                        wmma::mma_sync(acc[i][j], fah[i], fbh, acc[i][j]);
                        wmma::mma_sync(acc[i][j], fah[i], fbl, acc[i][j]);
                        wmma::mma_sync(acc[i][j], fal[i], fbh, acc[i][j]);
                    }
                }
            }
        }
        __syncthreads();

        if (c + 1 < NC) {
            __nv_bfloat16* st = (__nv_bfloat16*)smraw + ((c + 1) & 1) * STAGE;
            #pragma unroll
            for (int i = 0; i < NA4; i++) {
                int lin = tid + i * 256, r = lin >> 3, g = lin & 7;
                uint4 p = pa[i];
                uint2 hv = make_uint2(__byte_perm(p.x, p.y, 0x5410), __byte_perm(p.z, p.w, 0x5410));
                uint2 lv = make_uint2(__byte_perm(p.x, p.y, 0x7632), __byte_perm(p.z, p.w, 0x7632));
                *(uint2*)(st + r * LDS_ + g * 4) = hv;
                *(uint2*)(st + ASZ + r * LDS_ + g * 4) = lv;
            }
            #pragma unroll
            for (int i = 0; i < NB4; i++) {
                int lin = tid + i * 256, r = lin >> 3, g = lin & 7;
                uint4 p = pb[i];
                uint2 hv = make_uint2(__byte_perm(p.x, p.y, 0x5410), __byte_perm(p.z, p.w, 0x5410));
                uint2 lv = make_uint2(__byte_perm(p.x, p.y, 0x7632), __byte_perm(p.z, p.w, 0x7632));
                *(uint2*)(st + 2 * ASZ + r * LDS_ + g * 4) = hv;
                *(uint2*)(st + 2 * ASZ + BSZ + r * LDS_ + g * 4) = lv;
            }
            __syncthreads();
        }
    }

    // ---- epilogue ----
    if (!Cp) {
        float* Cb = C + coff;
        #pragma unroll
        for (int i = 0; i < 2; i++)
            #pragma unroll
            for (int j = 0; j < NT; j++)
                wmma::store_matrix_sync(
                    Cb + (long)(row0 + wm * 32 + i * 16) * ldc + col0 + wn * WN + j * 16,
                    acc[i][j], ldc, wmma::mem_row_major);
    } else {
        __syncthreads();
        float* wbuf = (float*)smraw + wid * 256;
        uint32_t* Cb = Cp + coff;
        #pragma unroll
        for (int i = 0; i < 2; i++)
            #pragma unroll
            for (int j = 0; j < NT; j++) {
                wmma::store_matrix_sync(wbuf, acc[i][j], 16, wmma::mem_row_major);
                __syncwarp();
                int r = lane >> 1, ch = lane & 1;
                const float* src = wbuf + r * 16 + ch * 8;
                uint32_t pk[8];
                #pragma unroll
                for (int t = 0; t < 8; t++) pk[t] = packf(src[t]);
                long off = (long)(row0 + wm * 32 + i * 16 + r) * ldc + col0 + wn * WN + j * 16 + ch * 8;
                *(uint4*)(Cb + off) = make_uint4(pk[0], pk[1], pk[2], pk[3]);
                *(uint4*)(Cb + off + 4) = make_uint4(pk[4], pk[5], pk[6], pk[7]);
                __syncwarp();
            }
    }
}

// ---------------------------------------------------------------------------
// Aux kernels
// ---------------------------------------------------------------------------
__global__ void embed_k(const int* __restrict__ tokens, const float* __restrict__ emb,
                        float* __restrict__ y) {
    int r = blockIdx.x;
    int tok = tokens[r];
    const float4* src = (const float4*)(emb + (long)tok * Dc);
    float4* dst = (float4*)(y + (long)r * Dc);
    for (int i = threadIdx.x; i < Dc / 4; i += blockDim.x) dst[i] = src[i];
}

__global__ void rmsnorm_pack(const float* __restrict__ in, const float* __restrict__ w,
                             uint32_t* __restrict__ out) {
    long b = (long)blockIdx.x * Dc;
    float s = 0.0f;
    for (int i = threadIdx.x; i < Dc; i += 256) { float v = in[b + i]; s += v * v; }
    s = blockReduceSum(s);
    float inv = rsqrtf(s * (1.0f / Dc) + 1e-6f);
    for (int i = threadIdx.x; i < Dc; i += 256) out[b + i] = packf(in[b + i] * inv * w[i]);
}

__global__ void rope_pack(const float* __restrict__ q, const float* __restrict__ k,
                          uint32_t* __restrict__ q2, uint32_t* __restrict__ k2) {
    int idx = blockIdx.x * 256 + threadIdx.x;    // over B*L*H*32
    int i = idx & 31;
    int rest = idx >> 5;
    int h = rest & (Hc - 1);
    int rl = rest >> 4;
    int l = rl & (Lc - 1);
    float ts = powf(10000.0f, (float)i * (1.0f / 32.0f));
    float ang = (float)l / ts;
    float sn = sinf(ang), cs = cosf(ang);
    long base = (long)rl * Dc + h * DHc + i;
    float q1 = q[base], qb = q[base + 32];
    q2[base]      = packf((q1 * cs - qb * sn) * 0.125f);
    q2[base + 32] = packf((qb * cs + q1 * sn) * 0.125f);
    float k1 = k[base], kb = k[base + 32];
    k2[base]      = packf(k1 * cs - kb * sn);
    k2[base + 32] = packf(kb * cs + k1 * sn);
}

__global__ void vtrans_pack(const float* __restrict__ v, uint32_t* __restrict__ vt) {
    __shared__ uint32_t t[32][33];
    int bh = blockIdx.z; int b = bh >> 4, h = bh & 15;
    int l0 = blockIdx.x * 32, d0 = blockIdx.y * 32;
    int tx = threadIdx.x, ty = threadIdx.y;
    float val = v[(long)(b * Lc + l0 + ty) * Dc + h * DHc + d0 + tx];
    t[ty][tx] = packf(val);
    __syncthreads();
    vt[((long)bh * DHc + d0 + ty) * Lc + l0 + tx] = t[tx][ty];
}

__global__ void softmax_pack(const float* __restrict__ att, uint32_t* __restrict__ out) {
    int qi = blockIdx.x;
    long base = ((long)blockIdx.y * Lc + qi) * Lc;
    int tid = threadIdx.x;
    float vals[4];
    float mx = -FLT_MAX;
    #pragma unroll
    for (int j = 0; j < 4; j++) {
        int kk = tid + j * 256;
        vals[j] = (kk <= qi) ? att[base + kk] : -FLT_MAX;
        mx = fmaxf(mx, vals[j]);
    }
    mx = blockReduceMax(mx);
    float s = 0.0f;
    #pragma unroll
    for (int j = 0; j < 4; j++) {
        int kk = tid + j * 256;
        if (kk <= qi) { vals[j] = expf(vals[j] - mx); s += vals[j]; }
        else vals[j] = 0.0f;
    }
    s = blockReduceSum(s);
    float inv = 1.0f / s;
    int lim = (qi | 127) + 1;
    #pragma unroll
    for (int j = 0; j < 4; j++) {
        int kk = tid + j * 256;
        if (kk < lim) out[base + kk] = packf(vals[j] * inv);
    }
}

__global__ void swish_pack(const float* __restrict__ g, const float* __restrict__ p,
                           uint32_t* __restrict__ o) {
    int i = blockIdx.x * 256 + threadIdx.x;
    float gv = g[i], pv = p[i];
    o[i] = packf(gv / (1.0f + expf(-gv)) * pv);
}

// Transpose + pack: W [Kd][Nd] fp32 -> O [Nd][Kd] u32, batched over layers (z)
__global__ void wtrans(const float* __restrict__ W, uint32_t* __restrict__ O, int Kd, int Nd) {
    __shared__ uint32_t t[32][33];
    long lo = (long)blockIdx.z * Kd * Nd;
    int n0 = blockIdx.x * 32, k0 = blockIdx.y * 32;
    int tx = threadIdx.x, ty = threadIdx.y;
    t[ty][tx] = packf(W[lo + (long)(k0 + ty) * Nd + n0 + tx]);
    __syncthreads();
    O[lo + (long)(n0 + ty) * Kd + k0 + tx] = t[tx][ty];
}

// ---------------------------------------------------------------------------
// Host
// ---------------------------------------------------------------------------
#define SM128 81920
#define SM64  61440

extern "C" void kernel_launch(void* const* d_in, const int* in_sizes, int n_in,
                              void* d_out, int out_size) {
    const int*   tokens = (const int*)d_in[0];
    const float* embed  = (const float*)d_in[1];
    const float* ln1    = (const float*)d_in[2];
    const float* Wq     = (const float*)d_in[3];
    const float* Wk     = (const float*)d_in[4];
    const float* Wv     = (const float*)d_in[5];
    const float* Wo     = (const float*)d_in[6];
    const float* ln2    = (const float*)d_in[7];
    const float* Wg     = (const float*)d_in[8];
    const float* Wp     = (const float*)d_in[9];
    const float* Wd     = (const float*)d_in[10];
    const float* out_ln = (const float*)d_in[11];
    const float* head   = (const float*)d_in[12];

    cudaFuncSetAttribute(gemm_mma<128>, cudaFuncAttributeMaxDynamicSharedMemorySize, SM128);
    cudaFuncSetAttribute(gemm_mma<64>,  cudaFuncAttributeMaxDynamicSharedMemorySize, SM64);

    float *y, *q, *k, *v, *att, *gf, *pf;
    uint32_t *x2, *q2, *k2, *vt2, *t2, *p2, *g2, *w2;
    cudaGetSymbolAddress((void**)&y,   g_y);
    cudaGetSymbolAddress((void**)&q,   g_q);
    cudaGetSymbolAddress((void**)&k,   g_k);
    cudaGetSymbolAddress((void**)&v,   g_v);
    cudaGetSymbolAddress((void**)&att, g_att);
    cudaGetSymbolAddress((void**)&gf,  g_gf);
    cudaGetSymbolAddress((void**)&pf,  g_pf);
    cudaGetSymbolAddress((void**)&x2,  g_x2);
    cudaGetSymbolAddress((void**)&q2,  g_q2);
    cudaGetSymbolAddress((void**)&k2,  g_k2);
    cudaGetSymbolAddress((void**)&vt2, g_vt2);
    cudaGetSymbolAddress((void**)&t2,  g_t2);
    cudaGetSymbolAddress((void**)&p2,  g_p2);
    cudaGetSymbolAddress((void**)&g2,  g_g2);
    cudaGetSymbolAddress((void**)&w2,  g_w2);

    const long OQ = 0, OK_ = 8388608, OV = 16777216, OO = 25165824;
    const long OG = 33554432, OP = 67108864, OD = 100663296, OH = 134217728;

    dim3 tb(32, 32);
    wtrans<<<dim3(32, 32, 8),   tb>>>(Wq,   w2 + OQ,  1024, 1024);
    wtrans<<<dim3(32, 32, 8),   tb>>>(Wk,   w2 + OK_, 1024, 1024);
    wtrans<<<dim3(32, 32, 8),   tb>>>(Wv,   w2 + OV,  1024, 1024);
    wtrans<<<dim3(32, 32, 8),   tb>>>(Wo,   w2 + OO,  1024, 1024);
    wtrans<<<dim3(128, 32, 8),  tb>>>(Wg,   w2 + OG,  1024, 4096);
    wtrans<<<dim3(128, 32, 8),  tb>>>(Wp,   w2 + OP,  1024, 4096);
    wtrans<<<dim3(32, 128, 8),  tb>>>(Wd,   w2 + OD,  4096, 1024);
    wtrans<<<dim3(1000, 32, 1), tb>>>(head, w2 + OH,  1024, 32000);

    embed_k<<<Bc * Lc, 256>>>(tokens, embed, y);

    const long LL = (long)Lc * Lc;
    const long LD = (long)Lc * Dc;

    for (int l = 0; l < NL; l++) {
        rmsnorm_pack<<<Bc * Lc, 256>>>(y, ln1 + (long)l * Dc, x2);

        gemm_mma<128><<<dim3(8, 16, 1), 256, SM128>>>(x2, w2 + OQ + (long)l * 1048576, q, 0, 0,
            1024, 1024, 1024, 1024, 1, 0, 0, 0, 0, 0, 0, 0);
        gemm_mma<128><<<dim3(8, 16, 1), 256, SM128>>>(x2, w2 + OK_ + (long)l * 1048576, k, 0, 0,
            1024, 1024, 1024, 1024, 1, 0, 0, 0, 0, 0, 0, 0);
        gemm_mma<128><<<dim3(8, 16, 1), 256, SM128>>>(x2, w2 + OV + (long)l * 1048576, v, 0, 0,
            1024, 1024, 1024, 1024, 1, 0, 0, 0, 0, 0, 0, 0);

        rope_pack<<<4096, 256>>>(q, k, q2, k2);
        vtrans_pack<<<dim3(32, 2, 32), tb>>>(v, vt2);

        // scores: att[b,h,qi,ki], causal tiles skipped
        gemm_mma<128><<<dim3(8, 8, 32), 256, SM128>>>(q2, k2, att, 0, 0,
            64, 1024, 1024, 1024, Hc,
            LD, 64, LD, 64, (long)Hc * LL, LL, 2);

        softmax_pack<<<dim3(Lc, Bc * Hc), 256>>>(att, p2);

        // AV: t[b,qi,h,dh] (packed out), K clipped per M-tile
        gemm_mma<64><<<dim3(1, 8, 32), 256, SM64>>>(p2, vt2, 0, t2, 0,
            1024, 1024, 1024, 1024, Hc,
            (long)Hc * LL, LL, (long)Hc * DHc * Lc, (long)DHc * Lc, LD, 64, 4);

        // y += t @ Wo
        gemm_mma<128><<<dim3(8, 16, 1), 256, SM128>>>(t2, w2 + OO + (long)l * 1048576, y, 0, y,
            1024, 1024, 1024, 1024, 1, 0, 0, 0, 0, 0, 0, 0);

        rmsnorm_pack<<<Bc * Lc, 256>>>(y, ln2 + (long)l * Dc, x2);

        gemm_mma<128><<<dim3(32, 16, 1), 256, SM128>>>(x2, w2 + OG + (long)l * 4194304, gf, 0, 0,
            1024, 1024, 1024, 4096, 1, 0, 0, 0, 0, 0, 0, 0);
        gemm_mma<128><<<dim3(32, 16, 1), 256, SM128>>>(x2, w2 + OP + (long)l * 4194304, pf, 0, 0,
            1024, 1024, 1024, 4096, 1, 0, 0, 0, 0, 0, 0, 0);

        swish_pack<<<32768, 256>>>(gf, pf, g2);

        // y += h @ Wd
        gemm_mma<128><<<dim3(8, 16, 1), 256, SM128>>>(g2, w2 + OD + (long)l * 4194304, y, 0, y,
            4096, 4096, 4096, 1024, 1, 0, 0, 0, 0, 0, 0, 0);
    }

    rmsnorm_pack<<<Bc * Lc, 256>>>(y, out_ln, x2);
    gemm_mma<128><<<dim3(250, 16, 1), 256, SM128>>>(x2, w2 + OH, (float*)d_out, 0, 0,
        1024, 1024, 1024, 32000, 1, 0, 0, 0, 0, 0, 0, 0);
}

// round 5
// speedup vs baseline: 2.2672x; 1.1472x over previous
#include <cuda_runtime.h>
#include <cuda_bf16.h>
#include <mma.h>
#include <math.h>
#include <float.h>
#include <stdint.h>

using namespace nvcuda;

#define Bc 2
#define Lc 1024
#define Dc 1024
#define Hc 16
#define NL 8
#define Vc 32000
#define Fc 4096
#define DHc 64

// ---------------------------------------------------------------------------
// Device-global scratch
// ---------------------------------------------------------------------------
__device__ float g_y[Bc*Lc*Dc];
__device__ float g_qkv[Bc*Lc*3*Dc];
__device__ float g_att[Bc*Hc*Lc*Lc];
__device__ float g_gp[Bc*Lc*2*Fc];
// bf16 hi/lo planes
__device__ __nv_bfloat16 g_xh[Bc*Lc*Dc],  g_xl[Bc*Lc*Dc];
__device__ __nv_bfloat16 g_qh[Bc*Lc*Dc],  g_ql[Bc*Lc*Dc];
__device__ __nv_bfloat16 g_kh[Bc*Lc*Dc],  g_kl[Bc*Lc*Dc];
__device__ __nv_bfloat16 g_vth[Bc*Hc*DHc*Lc], g_vtl[Bc*Hc*DHc*Lc];
__device__ __nv_bfloat16 g_th[Bc*Lc*Dc],  g_tl[Bc*Lc*Dc];
__device__ __nv_bfloat16 g_ph[Bc*Hc*Lc*Lc], g_pl[Bc*Hc*Lc*Lc];
__device__ __nv_bfloat16 g_gh[Bc*Lc*Fc],  g_gl[Bc*Lc*Fc];
__device__ __nv_bfloat16 g_wh[166985728], g_wl[166985728];

__device__ __forceinline__ uint32_t packf(float v) {
    __nv_bfloat16 h = __float2bfloat16(v);
    float hf = __bfloat162float(h);
    __nv_bfloat16 l = __float2bfloat16(v - hf);
    return (uint32_t)__bfloat16_as_ushort(h) | ((uint32_t)__bfloat16_as_ushort(l) << 16);
}
__device__ __forceinline__ void packf2(float v, __nv_bfloat16& h, __nv_bfloat16& l) {
    h = __float2bfloat16(v);
    l = __float2bfloat16(v - __bfloat162float(h));
}

__device__ __forceinline__ uint32_t smem_u32(const void* p) {
    uint32_t a;
    asm("{ .reg .u64 t; cvta.to.shared.u64 t, %1; cvt.u32.u64 %0, t; }" : "=r"(a) : "l"(p));
    return a;
}
__device__ __forceinline__ void cpasync16(uint32_t dst, const void* src) {
    asm volatile("cp.async.cg.shared.global [%0], [%1], 16;" :: "r"(dst), "l"(src) : "memory");
}
__device__ __forceinline__ void cp_commit() {
    asm volatile("cp.async.commit_group;" ::: "memory");
}
__device__ __forceinline__ void cp_wait2() {
    asm volatile("cp.async.wait_group 2;" ::: "memory");
}

// ---------------------------------------------------------------------------
// Block reductions (blockDim.x == 256)
// ---------------------------------------------------------------------------
__device__ __forceinline__ float blockReduceSum(float v) {
    __shared__ float sh[33];
    int lane = threadIdx.x & 31, wid = threadIdx.x >> 5;
    #pragma unroll
    for (int o = 16; o > 0; o >>= 1) v += __shfl_down_sync(0xffffffffu, v, o);
    if (lane == 0) sh[wid] = v;
    __syncthreads();
    v = (threadIdx.x < 8) ? sh[lane] : 0.0f;
    if (wid == 0) {
        #pragma unroll
        for (int o = 4; o > 0; o >>= 1) v += __shfl_down_sync(0xffffffffu, v, o);
        if (lane == 0) sh[32] = v;
    }
    __syncthreads();
    return sh[32];
}
__device__ __forceinline__ float blockReduceMax(float v) {
    __shared__ float sh[33];
    int lane = threadIdx.x & 31, wid = threadIdx.x >> 5;
    #pragma unroll
    for (int o = 16; o > 0; o >>= 1) v = fmaxf(v, __shfl_down_sync(0xffffffffu, v, o));
    if (lane == 0) sh[wid] = v;
    __syncthreads();
    v = (threadIdx.x < 8) ? sh[lane] : -FLT_MAX;
    if (wid == 0) {
        #pragma unroll
        for (int o = 4; o > 0; o >>= 1) v = fmaxf(v, __shfl_down_sync(0xffffffffu, v, o));
        if (lane == 0) sh[32] = v;
    }
    __syncthreads();
    return sh[32];
}

// ---------------------------------------------------------------------------
// WMMA GEMM, cp.async 3-stage pipeline.
// D[M,N] = A[M,K] @ B[N,K]^T, bf16x3 (hi*hi + hi*lo + lo*hi), fp32 accum.
// A,B given as separate hi/lo bf16 planes, K-major rows.
// BM=128, BN in {128,64}, BK=32, 256 threads = 8 warps (4Mx2N).
// flags: bit1 = causal tile skip, bit2 = K clip to row0+128.
// Ch != null -> packed bf16 hi/lo output planes; else fp32 C (R folded in).
// ---------------------------------------------------------------------------
#define LDS_ 40     // smem row pitch in bf16 elems (64B data + 16B pad)

template<int BN>
__global__ __launch_bounds__(256) void gemm_mma(
    const __nv_bfloat16* __restrict__ Ahp, const __nv_bfloat16* __restrict__ Alp,
    const __nv_bfloat16* __restrict__ Bhp, const __nv_bfloat16* __restrict__ Blp,
    float* __restrict__ C, __nv_bfloat16* __restrict__ Ch, __nv_bfloat16* __restrict__ Cl,
    const float* __restrict__ R,
    int K, int lda, int ldb, int ldc, int bH,
    long sAb, long sAh, long sBb, long sBh, long sCb, long sCh, int flags)
{
    const int BM = 128;
    const int NT = BN / 32;
    const int WN = BN / 2;
    const int APB = 5120;            // A plane elems in smem (128*40)
    const int BPB = BN * LDS_;       // B plane elems
    const int SSZ = 2 * APB * 2 + 2 * BPB * 2;   // stage bytes

    int row0 = blockIdx.y * BM, col0 = blockIdx.x * BN;
    if ((flags & 2) && col0 >= row0 + BM) return;
    if (flags & 4) { int kc = row0 + BM; if (kc < K) K = kc; }
    int z = blockIdx.z, zb = z / bH, zh = z - zb * bH;
    long aoff = (long)zb * sAb + (long)zh * sAh;
    long boff = (long)zb * sBb + (long)zh * sBh;
    long coff = (long)zb * sCb + (long)zh * sCh;

    extern __shared__ __align__(16) char smraw[];
    uint32_t sbase = smem_u32(smraw);

    int tid = threadIdx.x, wid = tid >> 5, lane = tid & 31;
    int wm = wid & 3, wn = wid >> 2;

    wmma::fragment<wmma::accumulator, 16, 16, 16, float> acc[2][NT];
    if (R) {
        const float* Rb = R + coff;
        #pragma unroll
        for (int i = 0; i < 2; i++)
            #pragma unroll
            for (int j = 0; j < NT; j++)
                wmma::load_matrix_sync(acc[i][j],
                    Rb + (long)(row0 + wm * 32 + i * 16) * ldc + col0 + wn * WN + j * 16,
                    ldc, wmma::mem_row_major);
    } else {
        #pragma unroll
        for (int i = 0; i < 2; i++)
            #pragma unroll
            for (int j = 0; j < NT; j++)
                wmma::fill_fragment(acc[i][j], 0.0f);
    }

    const __nv_bfloat16* Ahg = Ahp + aoff + (long)row0 * lda;
    const __nv_bfloat16* Alg = Alp + aoff + (long)row0 * lda;
    const __nv_bfloat16* Bhg = Bhp + boff + (long)col0 * ldb;
    const __nv_bfloat16* Blg = Blp + boff + (long)col0 * ldb;
    int NC = K >> 5;

    // issue loads of K-chunk c into pipeline slot
    auto issue = [&](int c) {
        uint32_t sb = sbase + (c % 3) * SSZ;
        int kc = c << 5;
        #pragma unroll
        for (int i = 0; i < 2; i++) {
            int lin = tid + i * 256;
            int r = lin >> 2, g = lin & 3;
            long go = (long)r * lda + kc + g * 8;
            uint32_t so = r * 80 + g * 16;
            cpasync16(sb + so, Ahg + go);
            cpasync16(sb + 2 * APB + so, Alg + go);
        }
        #pragma unroll
        for (int i = 0; i < BN / 64; i++) {
            int lin = tid + i * 256;
            int r = lin >> 2, g = lin & 3;
            long go = (long)r * ldb + kc + g * 8;
            uint32_t so = r * 80 + g * 16;
            cpasync16(sb + 4 * APB + so, Bhg + go);
            cpasync16(sb + 4 * APB + 2 * BPB + so, Blg + go);
        }
    };

    #pragma unroll
    for (int s = 0; s < 3; s++) {
        if (s < NC) issue(s);
        cp_commit();
    }

    for (int c = 0; c < NC; c++) {
        cp_wait2();
        __syncthreads();
        {
            const __nv_bfloat16* base = (const __nv_bfloat16*)(smraw + (c % 3) * SSZ);
            const __nv_bfloat16* Ah = base;
            const __nv_bfloat16* Al = base + APB;
            const __nv_bfloat16* Bh = base + 2 * APB;
            const __nv_bfloat16* Bl = base + 2 * APB + BPB;
            #pragma unroll
            for (int ks = 0; ks < 2; ks++) {
                int k0 = ks * 16;
                wmma::fragment<wmma::matrix_a, 16, 16, 16, __nv_bfloat16, wmma::row_major> fah[2], fal[2];
                #pragma unroll
                for (int i = 0; i < 2; i++) {
                    wmma::load_matrix_sync(fah[i], Ah + (wm * 32 + i * 16) * LDS_ + k0, LDS_);
                    wmma::load_matrix_sync(fal[i], Al + (wm * 32 + i * 16) * LDS_ + k0, LDS_);
                }
                #pragma unroll
                for (int j = 0; j < NT; j++) {
                    wmma::fragment<wmma::matrix_b, 16, 16, 16, __nv_bfloat16, wmma::col_major> fbh, fbl;
                    wmma::load_matrix_sync(fbh, Bh + (wn * WN + j * 16) * LDS_ + k0, LDS_);
                    wmma::load_matrix_sync(fbl, Bl + (wn * WN + j * 16) * LDS_ + k0, LDS_);
                    #pragma unroll
                    for (int i = 0; i < 2; i++) {
                        wmma::mma_sync(acc[i][j], fah[i], fbh, acc[i][j]);
                        wmma::mma_sync(acc[i][j], fah[i], fbl, acc[i][j]);
                        wmma::mma_sync(acc[i][j], fal[i], fbh, acc[i][j]);
                    }
                }
            }
        }
        __syncthreads();
        if (c + 3 < NC) issue(c + 3);
        cp_commit();
    }

    // ---- epilogue ----
    if (!Ch) {
        float* Cb = C + coff;
        #pragma unroll
        for (int i = 0; i < 2; i++)
            #pragma unroll
            for (int j = 0; j < NT; j++)
                wmma::store_matrix_sync(
                    Cb + (long)(row0 + wm * 32 + i * 16) * ldc + col0 + wn * WN + j * 16,
                    acc[i][j], ldc, wmma::mem_row_major);
    } else {
        __syncthreads();
        float* wbuf = (float*)smraw + wid * 256;
        #pragma unroll
        for (int i = 0; i < 2; i++)
            #pragma unroll
            for (int j = 0; j < NT; j++) {
                wmma::store_matrix_sync(wbuf, acc[i][j], 16, wmma::mem_row_major);
                __syncwarp();
                int r = lane >> 1, chn = lane & 1;
                const float* src = wbuf + r * 16 + chn * 8;
                __nv_bfloat16 hb[8], lb[8];
                #pragma unroll
                for (int t = 0; t < 8; t++) packf2(src[t], hb[t], lb[t]);
                long off = (long)(row0 + wm * 32 + i * 16 + r) * ldc + col0 + wn * WN + j * 16 + chn * 8 + coff;
                *(uint4*)(Ch + off) = *(uint4*)hb;
                *(uint4*)(Cl + off) = *(uint4*)lb;
                __syncwarp();
            }
    }
}

// ---------------------------------------------------------------------------
// Aux kernels
// ---------------------------------------------------------------------------
__global__ void embed_k(const int* __restrict__ tokens, const float* __restrict__ emb,
                        float* __restrict__ y) {
    int r = blockIdx.x;
    int tok = tokens[r];
    const float4* src = (const float4*)(emb + (long)tok * Dc);
    float4* dst = (float4*)(y + (long)r * Dc);
    for (int i = threadIdx.x; i < Dc / 4; i += blockDim.x) dst[i] = src[i];
}

__global__ void rmsnorm_pack(const float* __restrict__ in, const float* __restrict__ w,
                             __nv_bfloat16* __restrict__ oh, __nv_bfloat16* __restrict__ ol) {
    long b = (long)blockIdx.x * Dc;
    float s = 0.0f;
    for (int i = threadIdx.x; i < Dc; i += 256) { float v = in[b + i]; s += v * v; }
    s = blockReduceSum(s);
    float inv = rsqrtf(s * (1.0f / Dc) + 1e-6f);
    for (int i = threadIdx.x; i < Dc; i += 256)
        packf2(in[b + i] * inv * w[i], oh[b + i], ol[b + i]);
}

// RoPE reads q,k from merged qkv buffer; writes hi/lo planes; q scaled 1/8
__global__ void rope_pack(const float* __restrict__ qkv,
                          __nv_bfloat16* __restrict__ qh, __nv_bfloat16* __restrict__ ql,
                          __nv_bfloat16* __restrict__ kh, __nv_bfloat16* __restrict__ kl) {
    int idx = blockIdx.x * 256 + threadIdx.x;   // over B*L*H*32
    int i = idx & 31;
    int rest = idx >> 5;
    int h = rest & (Hc - 1);
    int rl = rest >> 4;
    int l = rl & (Lc - 1);
    float ts = powf(10000.0f, (float)i * (1.0f / 32.0f));
    float ang = (float)l / ts;
    float sn = sinf(ang), cs = cosf(ang);
    long src = (long)rl * 3072 + h * DHc + i;
    long dst = (long)rl * Dc + h * DHc + i;
    float q1 = qkv[src], q2 = qkv[src + 32];
    packf2((q1 * cs - q2 * sn) * 0.125f, qh[dst], ql[dst]);
    packf2((q2 * cs + q1 * sn) * 0.125f, qh[dst + 32], ql[dst + 32]);
    float k1 = qkv[src + 1024], k2 = qkv[src + 1024 + 32];
    packf2(k1 * cs - k2 * sn, kh[dst], kl[dst]);
    packf2(k2 * cs + k1 * sn, kh[dst + 32], kl[dst + 32]);
}

__global__ void vtrans_pack(const float* __restrict__ qkv,
                            __nv_bfloat16* __restrict__ vh, __nv_bfloat16* __restrict__ vl) {
    __shared__ uint32_t t[32][33];
    int bh = blockIdx.z; int b = bh >> 4, h = bh & 15;
    int l0 = blockIdx.x * 32, d0 = blockIdx.y * 32;
    int tx = threadIdx.x, ty = threadIdx.y;
    float val = qkv[(long)(b * Lc + l0 + ty) * 3072 + 2048 + h * DHc + d0 + tx];
    t[ty][tx] = packf(val);
    __syncthreads();
    uint32_t p = t[tx][ty];
    long o = ((long)bh * DHc + d0 + ty) * Lc + l0 + tx;
    vh[o] = __ushort_as_bfloat16((unsigned short)(p & 0xFFFF));
    vl[o] = __ushort_as_bfloat16((unsigned short)(p >> 16));
}

__global__ void softmax_pack(const float* __restrict__ att,
                             __nv_bfloat16* __restrict__ oh, __nv_bfloat16* __restrict__ ol) {
    int qi = blockIdx.x;
    long base = ((long)blockIdx.y * Lc + qi) * Lc;
    int tid = threadIdx.x;
    float vals[4];
    float mx = -FLT_MAX;
    #pragma unroll
    for (int j = 0; j < 4; j++) {
        int kk = tid + j * 256;
        vals[j] = (kk <= qi) ? att[base + kk] : -FLT_MAX;
        mx = fmaxf(mx, vals[j]);
    }
    mx = blockReduceMax(mx);
    float s = 0.0f;
    #pragma unroll
    for (int j = 0; j < 4; j++) {
        int kk = tid + j * 256;
        if (kk <= qi) { vals[j] = expf(vals[j] - mx); s += vals[j]; }
        else vals[j] = 0.0f;
    }
    s = blockReduceSum(s);
    float inv = 1.0f / s;
    int lim = (qi | 127) + 1;
    #pragma unroll
    for (int j = 0; j < 4; j++) {
        int kk = tid + j * 256;
        if (kk < lim) packf2(vals[j] * inv, oh[base + kk], ol[base + kk]);
    }
}

__global__ void swish_pack(const float* __restrict__ gp,
                           __nv_bfloat16* __restrict__ oh, __nv_bfloat16* __restrict__ ol) {
    int i = blockIdx.x * 256 + threadIdx.x;     // over 2048*4096
    int row = i >> 12, col = i & 4095;
    float gv = gp[(long)row * 8192 + col];
    float pv = gp[(long)row * 8192 + 4096 + col];
    packf2(gv / (1.0f + expf(-gv)) * pv, oh[i], ol[i]);
}

// Transpose + split-pack: W [Kd][Nd] fp32 -> planes [Nd][Kd], per-layer out stride
__global__ void wtrans(const float* __restrict__ W,
                       __nv_bfloat16* __restrict__ Oh, __nv_bfloat16* __restrict__ Ol,
                       int Kd, int Nd, long ostride) {
    __shared__ uint32_t t[32][33];
    long li = (long)blockIdx.z * Kd * Nd;
    long lo_ = (long)blockIdx.z * ostride;
    int n0 = blockIdx.x * 32, k0 = blockIdx.y * 32;
    int tx = threadIdx.x, ty = threadIdx.y;
    t[ty][tx] = packf(W[li + (long)(k0 + ty) * Nd + n0 + tx]);
    __syncthreads();
    uint32_t p = t[tx][ty];
    long o = lo_ + (long)(n0 + ty) * Kd + k0 + tx;
    Oh[o] = __ushort_as_bfloat16((unsigned short)(p & 0xFFFF));
    Ol[o] = __ushort_as_bfloat16((unsigned short)(p >> 16));
}

// ---------------------------------------------------------------------------
// Host
// ---------------------------------------------------------------------------
#define SM128 (3 * (20480 + 128 * 160))   // 122880
#define SM64  (3 * (20480 + 64 * 160))    // 92160

extern "C" void kernel_launch(void* const* d_in, const int* in_sizes, int n_in,
                              void* d_out, int out_size) {
    const int*   tokens = (const int*)d_in[0];
    const float* embed  = (const float*)d_in[1];
    const float* ln1    = (const float*)d_in[2];
    const float* Wq     = (const float*)d_in[3];
    const float* Wk     = (const float*)d_in[4];
    const float* Wv     = (const float*)d_in[5];
    const float* Wo     = (const float*)d_in[6];
    const float* ln2    = (const float*)d_in[7];
    const float* Wg     = (const float*)d_in[8];
    const float* Wp     = (const float*)d_in[9];
    const float* Wd     = (const float*)d_in[10];
    const float* out_ln = (const float*)d_in[11];
    const float* head   = (const float*)d_in[12];

    cudaFuncSetAttribute(gemm_mma<128>, cudaFuncAttributeMaxDynamicSharedMemorySize, SM128);
    cudaFuncSetAttribute(gemm_mma<64>,  cudaFuncAttributeMaxDynamicSharedMemorySize, SM64);

    float *y, *qkv, *att, *gp;
    __nv_bfloat16 *xh, *xl, *qh, *ql, *kh, *kl, *vth, *vtl, *th, *tl, *ph, *pl, *gh, *gl, *wh, *wl;
    cudaGetSymbolAddress((void**)&y,   g_y);
    cudaGetSymbolAddress((void**)&qkv, g_qkv);
    cudaGetSymbolAddress((void**)&att, g_att);
    cudaGetSymbolAddress((void**)&gp,  g_gp);
    cudaGetSymbolAddress((void**)&xh,  g_xh);  cudaGetSymbolAddress((void**)&xl, g_xl);
    cudaGetSymbolAddress((void**)&qh,  g_qh);  cudaGetSymbolAddress((void**)&ql, g_ql);
    cudaGetSymbolAddress((void**)&kh,  g_kh);  cudaGetSymbolAddress((void**)&kl, g_kl);
    cudaGetSymbolAddress((void**)&vth, g_vth); cudaGetSymbolAddress((void**)&vtl, g_vtl);
    cudaGetSymbolAddress((void**)&th,  g_th);  cudaGetSymbolAddress((void**)&tl, g_tl);
    cudaGetSymbolAddress((void**)&ph,  g_ph);  cudaGetSymbolAddress((void**)&pl, g_pl);
    cudaGetSymbolAddress((void**)&gh,  g_gh);  cudaGetSymbolAddress((void**)&gl, g_gl);
    cudaGetSymbolAddress((void**)&wh,  g_wh);  cudaGetSymbolAddress((void**)&wl, g_wl);

    // weight layout (elements per plane)
    const long OQKV = 0;                       // 8 x [3072 x 1024]
    const long OO   = 25165824;                // 8 x [1024 x 1024]
    const long OGP  = 33554432;                // 8 x [8192 x 1024]
    const long OD   = 100663296;               // 8 x [1024 x 4096]
    const long OH   = 134217728;               // [32000 x 1024]

    dim3 tb(32, 32);
    wtrans<<<dim3(32, 32, 8),   tb>>>(Wq, wh + OQKV,            wl + OQKV,            1024, 1024, 3145728);
    wtrans<<<dim3(32, 32, 8),   tb>>>(Wk, wh + OQKV + 1048576,  wl + OQKV + 1048576,  1024, 1024, 3145728);
    wtrans<<<dim3(32, 32, 8),   tb>>>(Wv, wh + OQKV + 2097152,  wl + OQKV + 2097152,  1024, 1024, 3145728);
    wtrans<<<dim3(32, 32, 8),   tb>>>(Wo, wh + OO,              wl + OO,              1024, 1024, 1048576);
    wtrans<<<dim3(128, 32, 8),  tb>>>(Wg, wh + OGP,             wl + OGP,             1024, 4096, 8388608);
    wtrans<<<dim3(128, 32, 8),  tb>>>(Wp, wh + OGP + 4194304,   wl + OGP + 4194304,   1024, 4096, 8388608);
    wtrans<<<dim3(32, 128, 8),  tb>>>(Wd, wh + OD,              wl + OD,              4096, 1024, 4194304);
    wtrans<<<dim3(1000, 32, 1), tb>>>(head, wh + OH,            wl + OH,              1024, 32000, 0);

    embed_k<<<Bc * Lc, 256>>>(tokens, embed, y);

    const long LL = (long)Lc * Lc;   // 1048576
    const long LD = (long)Lc * Dc;   // 1048576

    for (int l = 0; l < NL; l++) {
        rmsnorm_pack<<<Bc * Lc, 256>>>(y, ln1 + (long)l * Dc, xh, xl);

        // merged QKV: [2048 x 3072]
        gemm_mma<128><<<dim3(24, 16, 1), 256, SM128>>>(
            xh, xl, wh + OQKV + (long)l * 3145728, wl + OQKV + (long)l * 3145728,
            qkv, 0, 0, 0, 1024, 1024, 1024, 3072, 1, 0, 0, 0, 0, 0, 0, 0);

        rope_pack<<<4096, 256>>>(qkv, qh, ql, kh, kl);
        vtrans_pack<<<dim3(32, 2, 32), tb>>>(qkv, vth, vtl);

        // scores (causal tiles skipped)
        gemm_mma<128><<<dim3(8, 8, 32), 256, SM128>>>(
            qh, ql, kh, kl, att, 0, 0, 0,
            64, 1024, 1024, 1024, Hc,
            LD, 64, LD, 64, (long)Hc * LL, LL, 2);

        softmax_pack<<<dim3(Lc, Bc * Hc), 256>>>(att, ph, pl);

        // AV (K clipped per M-tile), packed output planes
        gemm_mma<64><<<dim3(1, 8, 32), 256, SM64>>>(
            ph, pl, vth, vtl, 0, th, tl, 0,
            1024, 1024, 1024, 1024, Hc,
            (long)Hc * LL, LL, (long)Hc * DHc * Lc, (long)DHc * Lc, LD, 64, 4);

        // y += t @ Wo
        gemm_mma<128><<<dim3(8, 16, 1), 256, SM128>>>(
            th, tl, wh + OO + (long)l * 1048576, wl + OO + (long)l * 1048576,
            y, 0, 0, y, 1024, 1024, 1024, 1024, 1, 0, 0, 0, 0, 0, 0, 0);

        rmsnorm_pack<<<Bc * Lc, 256>>>(y, ln2 + (long)l * Dc, xh, xl);

        // merged gate+proj: [2048 x 8192]
        gemm_mma<128><<<dim3(64, 16, 1), 256, SM128>>>(
            xh, xl, wh + OGP + (long)l * 8388608, wl + OGP + (long)l * 8388608,
            gp, 0, 0, 0, 1024, 1024, 1024, 8192, 1, 0, 0, 0, 0, 0, 0, 0);

        swish_pack<<<32768, 256>>>(gp, gh, gl);

        // y += h @ Wd
        gemm_mma<128><<<dim3(8, 16, 1), 256, SM128>>>(
            gh, gl, wh + OD + (long)l * 4194304, wl + OD + (long)l * 4194304,
            y, 0, 0, y, 4096, 4096, 4096, 1024, 1, 0, 0, 0, 0, 0, 0, 0);
    }

    rmsnorm_pack<<<Bc * Lc, 256>>>(y, out_ln, xh, xl);
    gemm_mma<128><<<dim3(250, 16, 1), 256, SM128>>>(
        xh, xl, wh + OH, wl + OH, (float*)d_out, 0, 0, 0,
        1024, 1024, 1024, 32000, 1, 0, 0, 0, 0, 0, 0, 0);
}